// round 6
// baseline (speedup 1.0000x reference)
#include <cuda_runtime.h>
#include <cstdint>

// Scalar DCP reduction via TMA bulk-copy pipeline.
// result = sum_{b,r,c} w(r)*w(c)*|min over 3 channels of x[b,ch,r,c]|
// w = 2 at index 0 or 1023, else 3. Zero padding contributes 0.
//
// Memory is driven by cp.async.bulk (UBLKCP) into a 2-stage smem pipeline:
// outstanding bytes are decoupled from register count / warp count, so DRAM
// latency is hidden by pipeline depth instead of occupancy.

#define TPB        512
#define GRID       296u                   // 148 SMs * 2 blocks
#define GROUP_ROWS 4u
#define NGROUPS    4096u                  // 16*1024 rows / 4
#define CH         1048576u               // floats per channel (1024*1024)
#define CH_FLOATS  (GROUP_ROWS * 1024u)   // 4096 floats / channel / stage
#define CHAN_BYTES (CH_FLOATS * 4u)       // 16384
#define STAGE_FLOATS (3u * CH_FLOATS)     // 12288
#define STAGE_BYTES  (STAGE_FLOATS * 4u)  // 49152
#define SMEM_DYN   (2u * STAGE_BYTES + 32u)

__device__ float    g_part[GRID];
__device__ unsigned g_ticket;             // zero-init; wraps to 0 each run

__device__ __forceinline__ unsigned smem_u32(const void* p) {
    return (unsigned)__cvta_generic_to_shared(p);
}

__device__ __forceinline__ void bar_wait(unsigned bar, unsigned phase) {
    asm volatile(
        "{\n\t.reg .pred P;\n\t"
        "WAIT_%=:\n\t"
        "mbarrier.try_wait.parity.acquire.cta.shared::cta.b64 P, [%0], %1, 0x989680;\n\t"
        "@P bra DONE_%=;\n\t"
        "bra WAIT_%=;\n\t"
        "DONE_%=:\n\t}"
        :: "r"(bar), "r"(phase) : "memory");
}

extern __shared__ float sbuf[];

__global__ __launch_bounds__(TPB) void dcp_kernel(const float* __restrict__ x,
                                                  float* __restrict__ out) {
    uint64_t* mbar = (uint64_t*)(sbuf + 2 * STAGE_FLOATS);
    const unsigned tid = threadIdx.x;
    const unsigned bid = blockIdx.x;

    if (tid == 0) {
        asm volatile("mbarrier.init.shared.b64 [%0], 1;"
                     :: "r"(smem_u32(&mbar[0])) : "memory");
        asm volatile("mbarrier.init.shared.b64 [%0], 1;"
                     :: "r"(smem_u32(&mbar[1])) : "memory");
    }
    __syncthreads();

    // groups for this block: j = bid + k*GRID, k = 0..n-1
    const unsigned n = (NGROUPS - bid + GRID - 1u) / GRID;   // 13 or 14

    auto issue = [&](unsigned j, unsigned stage) {
        unsigned b  = j >> 8;                 // 256 groups per batch
        unsigned r0 = (j & 255u) << 2;        // first row of group
        const float* src = x + (unsigned long long)b * 3u * CH + r0 * 1024u;
        unsigned dst = smem_u32(sbuf + stage * STAGE_FLOATS);
        unsigned bar = smem_u32(&mbar[stage]);
        asm volatile("mbarrier.arrive.expect_tx.shared.b64 _, [%0], %1;"
                     :: "r"(bar), "r"(STAGE_BYTES) : "memory");
        #pragma unroll
        for (int c = 0; c < 3; c++) {
            asm volatile(
                "cp.async.bulk.shared::cta.global.mbarrier::complete_tx::bytes "
                "[%0], [%1], %2, [%3];"
                :: "r"(dst + c * CHAN_BYTES), "l"(src + c * CH),
                   "r"(CHAN_BYTES), "r"(bar) : "memory");
        }
    };

    if (tid == 0) {
        issue(bid, 0);
        if (n > 1) issue(bid + GRID, 1);
    }

    unsigned ph0 = 0, ph1 = 0;
    float tsum = 0.f;

    for (unsigned k = 0; k < n; k++) {
        unsigned stage = k & 1u;
        if (stage == 0) { bar_wait(smem_u32(&mbar[0]), ph0); ph0 ^= 1u; }
        else            { bar_wait(smem_u32(&mbar[1]), ph1); ph1 ^= 1u; }

        unsigned j  = bid + k * GRID;
        unsigned r0 = (j & 255u) << 2;
        const float4* b0 = (const float4*)(sbuf + stage * STAGE_FLOATS);
        const float4* b1 = b0 + (CH_FLOATS >> 2);
        const float4* b2 = b1 + (CH_FLOATS >> 2);

        #pragma unroll
        for (int q = 0; q < 2; q++) {
            unsigned v  = tid + q * TPB;      // 0..1023 vec4 in stage
            unsigned rg = v >> 8;             // row within group
            unsigned c4 = v & 255u;
            unsigned r  = r0 + rg;

            float4 a0 = b0[v];
            float4 a1 = b1[v];
            float4 a2 = b2[v];

            float m0 = fabsf(fminf(fminf(a0.x, a1.x), a2.x));
            float m1 = fabsf(fminf(fminf(a0.y, a1.y), a2.y));
            float m2 = fabsf(fminf(fminf(a0.z, a1.z), a2.z));
            float m3 = fabsf(fminf(fminf(a0.w, a1.w), a2.w));

            float wr = (r == 0u || r == 1023u) ? 2.f : 3.f;
            float w0 = (c4 == 0u)   ? 2.f : 3.f;
            float w3 = (c4 == 255u) ? 2.f : 3.f;

            float s = fmaf(w0, m0, fmaf(3.f, m1 + m2, w3 * m3));
            tsum = fmaf(wr, s, tsum);
        }

        __syncthreads();                      // all reads of this stage done
        if (tid == 0 && k + 2 < n) issue(bid + (k + 2) * GRID, stage);
    }

    // intra-block reduction
    #pragma unroll
    for (int ofs = 16; ofs > 0; ofs >>= 1)
        tsum += __shfl_xor_sync(0xFFFFFFFFu, tsum, ofs);

    __shared__ float warp_sums[TPB / 32];
    int lane = threadIdx.x & 31;
    int wid  = threadIdx.x >> 5;
    if (lane == 0) warp_sums[wid] = tsum;
    __syncthreads();

    __shared__ bool is_last;
    if (tid == 0) {
        float v = 0.f;
        #pragma unroll
        for (int w = 0; w < TPB / 32; w++) v += warp_sums[w];
        g_part[bid] = v;
        __threadfence();
        unsigned old = atomicInc(&g_ticket, GRID - 1u);   // self-resets
        is_last = (old == GRID - 1u);
    }
    __syncthreads();

    if (is_last) {
        double d = 0.0;
        for (int jj = (int)tid; jj < (int)GRID; jj += TPB)
            d += (double)g_part[jj];
        #pragma unroll
        for (int ofs = 16; ofs > 0; ofs >>= 1)
            d += __shfl_xor_sync(0xFFFFFFFFu, d, ofs);
        __shared__ double dsum[TPB / 32];
        if (lane == 0) dsum[wid] = d;
        __syncthreads();
        if (tid == 0) {
            double tot = 0.0;
            #pragma unroll
            for (int w = 0; w < TPB / 32; w++) tot += dsum[w];
            out[0] = (float)tot;
        }
    }
}

extern "C" void kernel_launch(void* const* d_in, const int* in_sizes, int n_in,
                              void* d_out, int out_size) {
    const float* x = (const float*)d_in[0];
    cudaFuncSetAttribute(dcp_kernel,
                         cudaFuncAttributeMaxDynamicSharedMemorySize, SMEM_DYN);
    dcp_kernel<<<GRID, TPB, SMEM_DYN>>>(x, (float*)d_out);
}

// round 7
// speedup vs baseline: 1.0576x; 1.0576x over previous
#include <cuda_runtime.h>

// Scalar DCP reduction, single kernel, last-block finalize.
// result = sum_{b,r,c} w(r)*w(c)*|min over 3 channels of x[b,ch,r,c]|
// w = 2 at index 0 or 1023, else 3. Zero padding contributes 0.
//
// Config: grid-stride, 512 thr x 592 blocks (4/SM, 2048 thr/SM, <=32 regs),
// streaming loads (__ldcs), single double atomicAdd per block + ticket
// finalize (self-resetting for graph replay).

#define TPB   512
#define GRID  592u              // 148 SMs * 4 blocks -> exactly one wave
#define N4    4194304u          // 16*1024*256 vec4 positions
#define CH4   262144u           // 2^18 float4 per channel

__device__ double   g_sum;      // zero-init; reset by last block each run
__device__ unsigned g_ticket;   // zero-init; wraps back to 0 each run

__global__ __launch_bounds__(TPB, 4) void dcp_kernel(const float* __restrict__ x,
                                                     float* __restrict__ out) {
    const unsigned stride = GRID * TPB;
    float tsum = 0.f;

    #pragma unroll 1
    for (unsigned i = blockIdx.x * TPB + threadIdx.x; i < N4; i += stride) {
        unsigned c4 = i & 255u;
        unsigned r  = (i >> 8) & 1023u;
        unsigned b  = i >> 18;

        const float4* p = (const float4*)x + (b * 3u << 18) + (r << 8) + c4;
        float4 a0 = __ldcs(p);
        float4 a1 = __ldcs(p + CH4);
        float4 a2 = __ldcs(p + 2u * CH4);

        float m0 = fabsf(fminf(fminf(a0.x, a1.x), a2.x));
        float m1 = fabsf(fminf(fminf(a0.y, a1.y), a2.y));
        float m2 = fabsf(fminf(fminf(a0.z, a1.z), a2.z));
        float m3 = fabsf(fminf(fminf(a0.w, a1.w), a2.w));

        float wr = (r == 0u || r == 1023u) ? 2.f : 3.f;
        float w0 = (c4 == 0u)   ? 2.f : 3.f;   // col 0 lives in first vec
        float w3 = (c4 == 255u) ? 2.f : 3.f;   // col 1023 in last vec

        float s = fmaf(w0, m0, fmaf(3.f, m1 + m2, w3 * m3));
        tsum = fmaf(wr, s, tsum);
    }

    // intra-block reduction
    #pragma unroll
    for (int ofs = 16; ofs > 0; ofs >>= 1)
        tsum += __shfl_xor_sync(0xFFFFFFFFu, tsum, ofs);

    __shared__ float warp_sums[TPB / 32];
    int lane = threadIdx.x & 31;
    int wid  = threadIdx.x >> 5;
    if (lane == 0) warp_sums[wid] = tsum;
    __syncthreads();

    if (threadIdx.x == 0) {
        float v = 0.f;
        #pragma unroll
        for (int w = 0; w < TPB / 32; w++) v += warp_sums[w];

        atomicAdd(&g_sum, (double)v);
        __threadfence();
        unsigned old = atomicInc(&g_ticket, GRID - 1u);   // wraps -> self-reset
        if (old == GRID - 1u) {
            // atomic read of the completed total (all adds ordered before
            // their ticket increments; atomicAdd(0) gives a coherent read)
            double tot = atomicAdd(&g_sum, 0.0);
            out[0] = (float)tot;
            g_sum = 0.0;            // reset for next graph replay
            __threadfence();
        }
    }
}

extern "C" void kernel_launch(void* const* d_in, const int* in_sizes, int n_in,
                              void* d_out, int out_size) {
    const float* x = (const float*)d_in[0];
    dcp_kernel<<<GRID, TPB>>>(x, (float*)d_out);
}

// round 8
// speedup vs baseline: 1.3722x; 1.2975x over previous
#include <cuda_runtime.h>

// Scalar DCP reduction, single kernel, last-block finalize.
// result = sum_{b,r,c} w(r)*w(c)*|min over 3 channels of x[b,ch,r,c]|
// w = 2 at index 0 or 1023, else 3. Zero padding contributes 0.
//
// Config: grid-stride, 512 thr x 592 blocks (4/SM, 2048 thr/SM, <=32 regs),
// streaming loads (__ldcs) + L2 prefetch of next iteration (MLP without
// register cost), atomicAdd(double)+ticket finalize (graph-replay safe).

#define TPB   512
#define GRID  592u              // 148 SMs * 4 blocks -> exactly one wave
#define N4    4194304u          // 16*1024*256 vec4 positions
#define CH4   262144u           // 2^18 float4 per channel
#define OFFM  0x3FFFFu          // mask: offset within one channel image

__device__ double   g_sum;      // zero-init; reset by last block each run
__device__ unsigned g_ticket;   // zero-init; wraps back to 0 each run

__global__ __launch_bounds__(TPB, 4) void dcp_kernel(const float* __restrict__ x,
                                                     float* __restrict__ out) {
    const unsigned stride = GRID * TPB;
    const float4* x4 = (const float4*)x;
    float tsum = 0.f;

    #pragma unroll 1
    for (unsigned i = blockIdx.x * TPB + threadIdx.x; i < N4; i += stride) {
        unsigned c4 = i & 255u;
        unsigned r  = (i >> 8) & 1023u;
        unsigned b  = i >> 18;

        const float4* p = x4 + (b * 3u << 18) + (i & OFFM);

        // prefetch next iteration's three lines into L2 (no reg, no SB)
        unsigned i2 = i + stride;
        if (i2 < N4) {
            const float4* q = x4 + ((i2 >> 18) * 3u << 18) + (i2 & OFFM);
            asm volatile("prefetch.global.L2 [%0];" :: "l"(q));
            asm volatile("prefetch.global.L2 [%0];" :: "l"(q + CH4));
            asm volatile("prefetch.global.L2 [%0];" :: "l"(q + 2u * CH4));
        }

        float4 a0 = __ldcs(p);
        float4 a1 = __ldcs(p + CH4);
        float4 a2 = __ldcs(p + 2u * CH4);

        float m0 = fabsf(fminf(fminf(a0.x, a1.x), a2.x));
        float m1 = fabsf(fminf(fminf(a0.y, a1.y), a2.y));
        float m2 = fabsf(fminf(fminf(a0.z, a1.z), a2.z));
        float m3 = fabsf(fminf(fminf(a0.w, a1.w), a2.w));

        float wr = (r == 0u || r == 1023u) ? 2.f : 3.f;
        float w0 = (c4 == 0u)   ? 2.f : 3.f;   // col 0 lives in first vec
        float w3 = (c4 == 255u) ? 2.f : 3.f;   // col 1023 in last vec

        float s = fmaf(w0, m0, fmaf(3.f, m1 + m2, w3 * m3));
        tsum = fmaf(wr, s, tsum);
    }

    // intra-block reduction
    #pragma unroll
    for (int ofs = 16; ofs > 0; ofs >>= 1)
        tsum += __shfl_xor_sync(0xFFFFFFFFu, tsum, ofs);

    __shared__ float warp_sums[TPB / 32];
    int lane = threadIdx.x & 31;
    int wid  = threadIdx.x >> 5;
    if (lane == 0) warp_sums[wid] = tsum;
    __syncthreads();

    if (threadIdx.x == 0) {
        float v = 0.f;
        #pragma unroll
        for (int w = 0; w < TPB / 32; w++) v += warp_sums[w];

        atomicAdd(&g_sum, (double)v);
        __threadfence();
        unsigned old = atomicInc(&g_ticket, GRID - 1u);   // wraps -> self-reset
        if (old == GRID - 1u) {
            double tot = atomicAdd(&g_sum, 0.0);          // coherent read
            out[0] = (float)tot;
            g_sum = 0.0;            // reset for next graph replay
            __threadfence();
        }
    }
}

extern "C" void kernel_launch(void* const* d_in, const int* in_sizes, int n_in,
                              void* d_out, int out_size) {
    const float* x = (const float*)d_in[0];
    dcp_kernel<<<GRID, TPB>>>(x, (float*)d_out);
}